// round 3
// baseline (speedup 1.0000x reference)
#include <cuda_runtime.h>

#define N_NODES 100000
#define N_EDGES 20000
#define NNZ     1600000
#define ESTRIDE 256   // max tracked nodes per edge (deg ~ Poisson(80))
#define NSTRIDE 64    // max tracked edges per node (deg ~ Poisson(16))

// ---------------- scratch (device globals; zero-initialized at module load) ----------
__device__ float g_eagg[(size_t)N_EDGES * 300];   // edge-aggregated input feats
__device__ float g_ew[(size_t)N_EDGES * 256];     // edge feats after W
__device__ float g_h[(size_t)N_NODES * 256];      // node activations
__device__ int   g_ecursor[N_EDGES];              // per-edge degree/cursor (zeroed by epilogue)
__device__ int   g_ncursor[N_NODES];              // per-node degree/cursor (zeroed by epilogue)
__device__ int   g_ebkt[(size_t)N_EDGES * ESTRIDE];   // per-edge node lists
__device__ int   g_nbkt[(size_t)N_NODES * NSTRIDE];   // per-node edge lists
__device__ float g_logits[N_NODES];
__device__ float g_partmax[12500];
__device__ float g_gmax;
__device__ float g_acc[129];                      // [0..127] weighted sum, [128]=Z (zeroed in maxred)

// ---------------- bucket CSR build (single kernel; cursors must be 0 on entry) --------
__global__ void build_kernel(const int* __restrict__ nidx, const int* __restrict__ eidx) {
    int i = blockIdx.x * blockDim.x + threadIdx.x;
    int stride = gridDim.x * blockDim.x;
    for (int j = i; j < NNZ; j += stride) {
        int n = nidx[j];
        int e = eidx[j];
        int p = atomicAdd(&g_ecursor[e], 1);
        if (p < ESTRIDE) g_ebkt[(size_t)e * ESTRIDE + p] = n;
        int q = atomicAdd(&g_ncursor[n], 1);
        if (q < NSTRIDE) g_nbkt[(size_t)n * NSTRIDE + q] = e;
    }
}

// ---------------- edge aggregation: eagg[e] = mean over member nodes of src row -------
// one warp per edge; lanes own float4 columns; unroll 4 rows for MLP
template <int F>
__global__ __launch_bounds__(256) void agg_edge_kernel(const float* __restrict__ src,
                                                       float* __restrict__ dst) {
    constexpr int F4 = F / 4;
    constexpr int V = (F4 + 31) / 32;
    int w = (blockIdx.x * blockDim.x + threadIdx.x) >> 5;
    int lane = threadIdx.x & 31;
    if (w >= N_EDGES) return;
    const int* lst = g_ebkt + (size_t)w * ESTRIDE;
    int tc = g_ecursor[w];
    int cnt = tc < ESTRIDE ? tc : ESTRIDE;
    float4 acc[V];
#pragma unroll
    for (int v = 0; v < V; v++) acc[v] = make_float4(0.f, 0.f, 0.f, 0.f);
    int i = 0;
    for (; i + 4 <= cnt; i += 4) {
        int n0 = lst[i], n1 = lst[i + 1], n2 = lst[i + 2], n3 = lst[i + 3];
        const float4* r0 = (const float4*)(src + (size_t)n0 * F);
        const float4* r1 = (const float4*)(src + (size_t)n1 * F);
        const float4* r2 = (const float4*)(src + (size_t)n2 * F);
        const float4* r3 = (const float4*)(src + (size_t)n3 * F);
#pragma unroll
        for (int v = 0; v < V; v++) {
            int c = lane + 32 * v;
            if (c < F4) {
                float4 t0 = r0[c], t1 = r1[c], t2 = r2[c], t3 = r3[c];
                acc[v].x += (t0.x + t1.x) + (t2.x + t3.x);
                acc[v].y += (t0.y + t1.y) + (t2.y + t3.y);
                acc[v].z += (t0.z + t1.z) + (t2.z + t3.z);
                acc[v].w += (t0.w + t1.w) + (t2.w + t3.w);
            }
        }
    }
    for (; i < cnt; i++) {
        int n0 = lst[i];
        const float4* r0 = (const float4*)(src + (size_t)n0 * F);
#pragma unroll
        for (int v = 0; v < V; v++) {
            int c = lane + 32 * v;
            if (c < F4) {
                float4 t0 = r0[c];
                acc[v].x += t0.x; acc[v].y += t0.y; acc[v].z += t0.z; acc[v].w += t0.w;
            }
        }
    }
    float inv = (tc > 0) ? 1.0f / (float)tc : 0.0f;
    float4* out = (float4*)(dst + (size_t)w * F);
#pragma unroll
    for (int v = 0; v < V; v++) {
        int c = lane + 32 * v;
        if (c < F4) {
            float4 o;
            o.x = acc[v].x * inv; o.y = acc[v].y * inv;
            o.z = acc[v].z * inv; o.w = acc[v].w * inv;
            out[c] = o;
        }
    }
}

// ---------------- node aggregation: h[n] = act(mean over member edges + bias) ---------
template <int F, bool LRELU>
__global__ __launch_bounds__(256) void agg_node_kernel(const float* __restrict__ src,
                                                       float* __restrict__ dst,
                                                       const float* __restrict__ bias) {
    constexpr int F4 = F / 4;
    constexpr int V = (F4 + 31) / 32;
    int w = (blockIdx.x * blockDim.x + threadIdx.x) >> 5;
    int lane = threadIdx.x & 31;
    if (w >= N_NODES) return;
    const int* lst = g_nbkt + (size_t)w * NSTRIDE;
    int tc = g_ncursor[w];
    int cnt = tc < NSTRIDE ? tc : NSTRIDE;
    float4 acc[V];
#pragma unroll
    for (int v = 0; v < V; v++) acc[v] = make_float4(0.f, 0.f, 0.f, 0.f);
    int i = 0;
    for (; i + 4 <= cnt; i += 4) {
        int e0 = lst[i], e1 = lst[i + 1], e2 = lst[i + 2], e3 = lst[i + 3];
        const float4* r0 = (const float4*)(src + (size_t)e0 * F);
        const float4* r1 = (const float4*)(src + (size_t)e1 * F);
        const float4* r2 = (const float4*)(src + (size_t)e2 * F);
        const float4* r3 = (const float4*)(src + (size_t)e3 * F);
#pragma unroll
        for (int v = 0; v < V; v++) {
            int c = lane + 32 * v;
            if (c < F4) {
                float4 t0 = r0[c], t1 = r1[c], t2 = r2[c], t3 = r3[c];
                acc[v].x += (t0.x + t1.x) + (t2.x + t3.x);
                acc[v].y += (t0.y + t1.y) + (t2.y + t3.y);
                acc[v].z += (t0.z + t1.z) + (t2.z + t3.z);
                acc[v].w += (t0.w + t1.w) + (t2.w + t3.w);
            }
        }
    }
    for (; i < cnt; i++) {
        int e0 = lst[i];
        const float4* r0 = (const float4*)(src + (size_t)e0 * F);
#pragma unroll
        for (int v = 0; v < V; v++) {
            int c = lane + 32 * v;
            if (c < F4) {
                float4 t0 = r0[c];
                acc[v].x += t0.x; acc[v].y += t0.y; acc[v].z += t0.z; acc[v].w += t0.w;
            }
        }
    }
    float inv = (tc > 0) ? 1.0f / (float)tc : 0.0f;
    const float4* b4 = (const float4*)bias;
    float4* out = (float4*)(dst + (size_t)w * F);
#pragma unroll
    for (int v = 0; v < V; v++) {
        int c = lane + 32 * v;
        if (c < F4) {
            float4 bb = b4[c];
            float4 o;
            o.x = acc[v].x * inv + bb.x;
            o.y = acc[v].y * inv + bb.y;
            o.z = acc[v].z * inv + bb.z;
            o.w = acc[v].w * inv + bb.w;
            if (LRELU) {
                o.x = (o.x > 0.f) ? o.x : 0.01f * o.x;
                o.y = (o.y > 0.f) ? o.y : 0.01f * o.y;
                o.z = (o.z > 0.f) ? o.z : 0.01f * o.z;
                o.w = (o.w > 0.f) ? o.w : 0.01f * o.w;
            }
            out[c] = o;
        }
    }
}

// ---------------- fp32 SGEMM: C[M,N] = A[M,K] @ B[K,N], row-major ----------------
// BM=128, BN=64, BK=8, 256 threads, 8x4 per thread
__global__ __launch_bounds__(256) void sgemm_kernel(const float* __restrict__ A,
                                                    const float* __restrict__ B,
                                                    float* __restrict__ C,
                                                    int M, int K, int N) {
    __shared__ float As[8][136];
    __shared__ float Bs[8][64];
    const int tid = threadIdx.x;
    const int bm = blockIdx.x * 128;
    const int bn = blockIdx.y * 64;
    const int a_row = tid >> 1;
    const int a_col = (tid & 1) * 4;
    const int b_row = tid >> 5;
    const int b_col = (tid & 31) * 2;
    const int ty = tid >> 4;
    const int tx = tid & 15;
    float acc[8][4];
#pragma unroll
    for (int i = 0; i < 8; i++)
#pragma unroll
        for (int j = 0; j < 4; j++) acc[i][j] = 0.f;

    const bool arow_ok = (bm + a_row) < M;
    const float* Ab = A + (size_t)(bm + a_row) * K;

    for (int kt = 0; kt < K; kt += 8) {
#pragma unroll
        for (int j = 0; j < 4; j++) {
            int k = kt + a_col + j;
            As[a_col + j][a_row] = (arow_ok && k < K) ? Ab[k] : 0.f;
        }
        {
            int k = kt + b_row;
            float2 bv = make_float2(0.f, 0.f);
            if (k < K) bv = *(const float2*)(B + (size_t)k * N + bn + b_col);
            *(float2*)&Bs[b_row][b_col] = bv;
        }
        __syncthreads();
#pragma unroll
        for (int k = 0; k < 8; k++) {
            float4 a0 = *(const float4*)&As[k][ty * 8];
            float4 a1 = *(const float4*)&As[k][ty * 8 + 4];
            float4 bv = *(const float4*)&Bs[k][tx * 4];
            float a[8] = {a0.x, a0.y, a0.z, a0.w, a1.x, a1.y, a1.z, a1.w};
            float b[4] = {bv.x, bv.y, bv.z, bv.w};
#pragma unroll
            for (int i = 0; i < 8; i++)
#pragma unroll
                for (int j = 0; j < 4; j++) acc[i][j] += a[i] * b[j];
        }
        __syncthreads();
    }
#pragma unroll
    for (int i = 0; i < 8; i++) {
        int r = bm + ty * 8 + i;
        if (r < M) {
            float4 o = make_float4(acc[i][0], acc[i][1], acc[i][2], acc[i][3]);
            *(float4*)(C + (size_t)r * N + bn + tx * 4) = o;
        }
    }
}

// ---------------- attention epilogue ----------------
// Also zeroes the bucket cursors for the next replay (grid covers 3.2M threads).
__global__ void logits_kernel(const float* __restrict__ h, const float* __restrict__ aw,
                              const float* __restrict__ ab) {
    __shared__ float smax[8];
    int gidx = blockIdx.x * blockDim.x + threadIdx.x;
    int gstride = gridDim.x * blockDim.x;
    for (int j = gidx; j < N_EDGES; j += gstride) g_ecursor[j] = 0;
    for (int j = gidx; j < N_NODES; j += gstride) g_ncursor[j] = 0;

    int w = gidx >> 5;
    int lane = threadIdx.x & 31;
    float lg = -1e30f;
    if (w < N_NODES) {
        float4 hv = ((const float4*)(h + (size_t)w * 128))[lane];
        float4 wv = ((const float4*)aw)[lane];
        float d = hv.x * wv.x + hv.y * wv.y + hv.z * wv.z + hv.w * wv.w;
#pragma unroll
        for (int off = 16; off > 0; off >>= 1) d += __shfl_xor_sync(0xffffffffu, d, off);
        d += ab[0];
        if (lane == 0) g_logits[w] = d;
        lg = d;
    }
    int wl = threadIdx.x >> 5;
    if (lane == 0) smax[wl] = lg;
    __syncthreads();
    if (threadIdx.x == 0) {
        float m = smax[0];
#pragma unroll
        for (int j = 1; j < 8; j++) m = fmaxf(m, smax[j]);
        g_partmax[blockIdx.x] = m;
    }
}

// global max of logits; also zeroes g_acc for the upcoming accum
__global__ void maxred_kernel(int nparts) {
    __shared__ float sm[32];
    if (threadIdx.x < 129) g_acc[threadIdx.x] = 0.0f;
    float m = -1e30f;
    for (int i = threadIdx.x; i < nparts; i += 1024) m = fmaxf(m, g_partmax[i]);
#pragma unroll
    for (int off = 16; off > 0; off >>= 1) m = fmaxf(m, __shfl_xor_sync(0xffffffffu, m, off));
    if ((threadIdx.x & 31) == 0) sm[threadIdx.x >> 5] = m;
    __syncthreads();
    if (threadIdx.x < 32) {
        float v = (threadIdx.x < ((1024 + 31) >> 5)) ? sm[threadIdx.x] : -1e30f;
#pragma unroll
        for (int off = 16; off > 0; off >>= 1) v = fmaxf(v, __shfl_xor_sync(0xffffffffu, v, off));
        if (threadIdx.x == 0) g_gmax = v;
    }
}

__global__ void accum_kernel(const float* __restrict__ h) {
    int t = threadIdx.x;           // 0..127 feature column
    float gmax = g_gmax;
    int per = (N_NODES + gridDim.x - 1) / gridDim.x;
    int n0 = blockIdx.x * per;
    int n1 = n0 + per;
    if (n1 > N_NODES) n1 = N_NODES;
    float acc = 0.f, z = 0.f;
    for (int n = n0; n < n1; n++) {
        float wgt = expf(g_logits[n] - gmax);
        acc += wgt * h[(size_t)n * 128 + t];
        z += wgt;
    }
    atomicAdd(&g_acc[t], acc);
    if (t == 0) atomicAdd(&g_acc[128], z);
}

__global__ void finalize_kernel(float* __restrict__ out) {
    int t = threadIdx.x;
    out[t] = g_acc[t] / g_acc[128];
}

// ---------------- launch ----------------
extern "C" void kernel_launch(void* const* d_in, const int* in_sizes, int n_in,
                              void* d_out, int out_size) {
    const float* x       = (const float*)d_in[0];          // [100000, 300]
    const int*   nidx    = (const int*)d_in[1];            // hyper_edge_index[0]
    const int*   eidx    = ((const int*)d_in[1]) + NNZ;    // hyper_edge_index[1]
    const float* W1      = (const float*)d_in[2];          // [300,256]
    const float* b1      = (const float*)d_in[3];
    const float* W2      = (const float*)d_in[4];          // [256,256]
    const float* b2      = (const float*)d_in[5];
    const float* W3      = (const float*)d_in[6];          // [256,128]
    const float* b3      = (const float*)d_in[7];
    const float* attn_W  = (const float*)d_in[8];          // [128,1]
    const float* attn_b  = (const float*)d_in[9];          // [1]
    float* out = (float*)d_out;                            // [128]

    // 1: bucket CSR build (cursors are zero: initially by load-time init,
    //    afterwards restored by logits_kernel each call)
    build_kernel<<<4096, 256>>>(nidx, eidx);

    // Layer 1: aggregate x (F=300) to edges, GEMM at edges, spread to nodes, lrelu
    agg_edge_kernel<300><<<2500, 256>>>(x, g_eagg);
    sgemm_kernel<<<dim3(157, 4), 256>>>(g_eagg, W1, g_ew, N_EDGES, 300, 256);
    agg_node_kernel<256, true><<<12500, 256>>>(g_ew, g_h, b1);   // <- ncu capture target

    // Layer 2
    agg_edge_kernel<256><<<2500, 256>>>(g_h, g_eagg);
    sgemm_kernel<<<dim3(157, 4), 256>>>(g_eagg, W2, g_ew, N_EDGES, 256, 256);
    agg_node_kernel<256, true><<<12500, 256>>>(g_ew, g_h, b2);

    // Layer 3 (no activation)
    agg_edge_kernel<256><<<2500, 256>>>(g_h, g_eagg);
    sgemm_kernel<<<dim3(157, 2), 256>>>(g_eagg, W3, g_ew, N_EDGES, 256, 128);
    agg_node_kernel<128, false><<<12500, 256>>>(g_ew, g_h, b3);

    // Attention pooling (softmax over nodes, weighted sum -> [128])
    logits_kernel<<<12500, 256>>>(g_h, attn_W, attn_b);
    maxred_kernel<<<1, 1024>>>(12500);
    accum_kernel<<<512, 128>>>(g_h);
    finalize_kernel<<<1, 128>>>(out);
}

// round 4
// speedup vs baseline: 1.1101x; 1.1101x over previous
#include <cuda_runtime.h>

#define N_NODES 100000
#define N_EDGES 20000
#define NNZ     1600000
#define ESTRIDE 256   // max tracked nodes per edge (deg ~ Poisson(80))
#define NSTRIDE 64    // max tracked edges per node (deg ~ Poisson(16))

// ---------------- scratch (device globals; zero-initialized at module load) ----------
__device__ float g_eagg[(size_t)N_EDGES * 300];   // edge-aggregated input feats
__device__ float g_ew[(size_t)N_EDGES * 256];     // edge feats after W
__device__ float g_h[(size_t)N_NODES * 256];      // node activations
__device__ int   g_ecursor[N_EDGES];              // per-edge degree (zeroed by logits epilogue)
__device__ int   g_ncursor[N_NODES];              // per-node degree (zeroed by logits epilogue)
__device__ int   g_ebkt[(size_t)N_EDGES * ESTRIDE];   // per-edge node lists
__device__ int   g_nbkt[(size_t)N_NODES * NSTRIDE];   // per-node edge lists
__device__ float g_logits[N_NODES];
__device__ float g_partmax[12500];
__device__ float g_gmax;
__device__ float g_acc[129];                      // [0..127] weighted sum, [128]=Z

// ---------------- bucket CSR build (cursors must be 0 on entry) ----------------------
__global__ void build_kernel(const int* __restrict__ nidx, const int* __restrict__ eidx) {
    int i = blockIdx.x * blockDim.x + threadIdx.x;
    int stride = gridDim.x * blockDim.x;
    for (int j = i; j < NNZ; j += stride) {
        int n = nidx[j];
        int e = eidx[j];
        int p = atomicAdd(&g_ecursor[e], 1);
        if (p < ESTRIDE) g_ebkt[(size_t)e * ESTRIDE + p] = n;
        int q = atomicAdd(&g_ncursor[n], 1);
        if (q < NSTRIDE) g_nbkt[(size_t)n * NSTRIDE + q] = e;
    }
}

// ---------------- tiny prep kernels (also shift ncu capture to agg_edge<300>) --------
__global__ void prep_a_kernel() {   // zero partmax (harmless; keeps launch slot)
    int i = blockIdx.x * blockDim.x + threadIdx.x;
    if (i < 12500) g_partmax[i] = -1e30f;
}
__global__ void prep_b_kernel() {   // zero attention accumulators for this call
    if (threadIdx.x < 129) g_acc[threadIdx.x] = 0.0f;
}

// ---------------- generic aggregation: warp per (row, 128-float chunk), MLP=8 --------
// EDGE=1: rows are hyperedges, gather node rows via g_ebkt (edge aggregation).
// EDGE=0: rows are nodes, gather edge rows via g_nbkt; adds bias (+ optional lrelu).
template <int F, int CHUNKS, int EDGE, bool LRELU>
__global__ __launch_bounds__(256) void agg_kernel(const float* __restrict__ src,
                                                  float* __restrict__ dst,
                                                  const float* __restrict__ bias) {
    const int ROWS   = EDGE ? N_EDGES : N_NODES;
    const int STRIDE = EDGE ? ESTRIDE : NSTRIDE;
    const int* __restrict__ cur = EDGE ? g_ecursor : g_ncursor;
    const int* __restrict__ bkt = EDGE ? g_ebkt    : g_nbkt;

    int w = (blockIdx.x * blockDim.x + threadIdx.x) >> 5;
    int lane = threadIdx.x & 31;
    int row = w / CHUNKS;
    int ch  = w % CHUNKS;
    if (row >= ROWS) return;

    const int* __restrict__ lst = bkt + (size_t)row * STRIDE;
    int tc  = cur[row];
    int cnt = tc < STRIDE ? tc : STRIDE;

    int colbase = ch * 128 + lane * 4;       // float offset of this lane's float4
    const bool active = colbase < F;         // partial last chunk (F=300 -> 44 floats)
    const float* __restrict__ sp = src + colbase;

    float4 acc = make_float4(0.f, 0.f, 0.f, 0.f);
    int i = 0;
    for (; i + 8 <= cnt; i += 8) {
        int idxreg = 0;
        if (lane < 8) idxreg = lst[i + lane];          // one 32B transaction
        int ns[8];
#pragma unroll
        for (int k = 0; k < 8; k++) ns[k] = __shfl_sync(0xffffffffu, idxreg, k);
        float4 t[8];
#pragma unroll
        for (int k = 0; k < 8; k++) {                  // 8 independent gathers in flight
            t[k] = make_float4(0.f, 0.f, 0.f, 0.f);
            if (active) t[k] = *(const float4*)(sp + (size_t)ns[k] * F);
        }
#pragma unroll
        for (int k = 0; k < 8; k++) {
            acc.x += t[k].x; acc.y += t[k].y; acc.z += t[k].z; acc.w += t[k].w;
        }
    }
    for (; i < cnt; i++) {                              // remainder (uniform broadcast idx)
        int n = lst[i];
        if (active) {
            float4 t = *(const float4*)(sp + (size_t)n * F);
            acc.x += t.x; acc.y += t.y; acc.z += t.z; acc.w += t.w;
        }
    }

    if (!active) return;
    float inv = (tc > 0) ? 1.0f / (float)tc : 0.0f;
    float4 o;
    o.x = acc.x * inv; o.y = acc.y * inv; o.z = acc.z * inv; o.w = acc.w * inv;
    if (!EDGE) {
        float4 bb = *(const float4*)(bias + colbase);
        o.x += bb.x; o.y += bb.y; o.z += bb.z; o.w += bb.w;
        if (LRELU) {
            o.x = (o.x > 0.f) ? o.x : 0.01f * o.x;
            o.y = (o.y > 0.f) ? o.y : 0.01f * o.y;
            o.z = (o.z > 0.f) ? o.z : 0.01f * o.z;
            o.w = (o.w > 0.f) ? o.w : 0.01f * o.w;
        }
    }
    *(float4*)(dst + (size_t)row * F + colbase) = o;
}

// ---------------- fp32 SGEMM: C[M,N] = A[M,K] @ B[K,N], row-major --------------------
__global__ __launch_bounds__(256) void sgemm_kernel(const float* __restrict__ A,
                                                    const float* __restrict__ B,
                                                    float* __restrict__ C,
                                                    int M, int K, int N) {
    __shared__ float As[8][136];
    __shared__ float Bs[8][64];
    const int tid = threadIdx.x;
    const int bm = blockIdx.x * 128;
    const int bn = blockIdx.y * 64;
    const int a_row = tid >> 1;
    const int a_col = (tid & 1) * 4;
    const int b_row = tid >> 5;
    const int b_col = (tid & 31) * 2;
    const int ty = tid >> 4;
    const int tx = tid & 15;
    float acc[8][4];
#pragma unroll
    for (int i = 0; i < 8; i++)
#pragma unroll
        for (int j = 0; j < 4; j++) acc[i][j] = 0.f;

    const bool arow_ok = (bm + a_row) < M;
    const float* Ab = A + (size_t)(bm + a_row) * K;

    for (int kt = 0; kt < K; kt += 8) {
#pragma unroll
        for (int j = 0; j < 4; j++) {
            int k = kt + a_col + j;
            As[a_col + j][a_row] = (arow_ok && k < K) ? Ab[k] : 0.f;
        }
        {
            int k = kt + b_row;
            float2 bv = make_float2(0.f, 0.f);
            if (k < K) bv = *(const float2*)(B + (size_t)k * N + bn + b_col);
            *(float2*)&Bs[b_row][b_col] = bv;
        }
        __syncthreads();
#pragma unroll
        for (int k = 0; k < 8; k++) {
            float4 a0 = *(const float4*)&As[k][ty * 8];
            float4 a1 = *(const float4*)&As[k][ty * 8 + 4];
            float4 bv = *(const float4*)&Bs[k][tx * 4];
            float a[8] = {a0.x, a0.y, a0.z, a0.w, a1.x, a1.y, a1.z, a1.w};
            float b[4] = {bv.x, bv.y, bv.z, bv.w};
#pragma unroll
            for (int i = 0; i < 8; i++)
#pragma unroll
                for (int j = 0; j < 4; j++) acc[i][j] += a[i] * b[j];
        }
        __syncthreads();
    }
#pragma unroll
    for (int i = 0; i < 8; i++) {
        int r = bm + ty * 8 + i;
        if (r < M) {
            float4 o = make_float4(acc[i][0], acc[i][1], acc[i][2], acc[i][3]);
            *(float4*)(C + (size_t)r * N + bn + tx * 4) = o;
        }
    }
}

// ---------------- attention epilogue -------------------------------------------------
// Also zeroes bucket cursors for the next replay (grid covers 3.2M threads).
__global__ void logits_kernel(const float* __restrict__ h, const float* __restrict__ aw,
                              const float* __restrict__ ab) {
    __shared__ float smax[8];
    int gidx = blockIdx.x * blockDim.x + threadIdx.x;
    int gstride = gridDim.x * blockDim.x;
    for (int j = gidx; j < N_EDGES; j += gstride) g_ecursor[j] = 0;
    for (int j = gidx; j < N_NODES; j += gstride) g_ncursor[j] = 0;

    int w = gidx >> 5;
    int lane = threadIdx.x & 31;
    float lg = -1e30f;
    if (w < N_NODES) {
        float4 hv = ((const float4*)(h + (size_t)w * 128))[lane];
        float4 wv = ((const float4*)aw)[lane];
        float d = hv.x * wv.x + hv.y * wv.y + hv.z * wv.z + hv.w * wv.w;
#pragma unroll
        for (int off = 16; off > 0; off >>= 1) d += __shfl_xor_sync(0xffffffffu, d, off);
        d += ab[0];
        if (lane == 0) g_logits[w] = d;
        lg = d;
    }
    int wl = threadIdx.x >> 5;
    if (lane == 0) smax[wl] = lg;
    __syncthreads();
    if (threadIdx.x == 0) {
        float m = smax[0];
#pragma unroll
        for (int j = 1; j < 8; j++) m = fmaxf(m, smax[j]);
        g_partmax[blockIdx.x] = m;
    }
}

__global__ void maxred_kernel(int nparts) {
    __shared__ float sm[32];
    float m = -1e30f;
    for (int i = threadIdx.x; i < nparts; i += 1024) m = fmaxf(m, g_partmax[i]);
#pragma unroll
    for (int off = 16; off > 0; off >>= 1) m = fmaxf(m, __shfl_xor_sync(0xffffffffu, m, off));
    if ((threadIdx.x & 31) == 0) sm[threadIdx.x >> 5] = m;
    __syncthreads();
    if (threadIdx.x < 32) {
        float v = sm[threadIdx.x];
#pragma unroll
        for (int off = 16; off > 0; off >>= 1) v = fmaxf(v, __shfl_xor_sync(0xffffffffu, v, off));
        if (threadIdx.x == 0) g_gmax = v;
    }
}

__global__ void accum_kernel(const float* __restrict__ h) {
    int t = threadIdx.x;           // 0..127 feature column
    float gmax = g_gmax;
    int per = (N_NODES + gridDim.x - 1) / gridDim.x;
    int n0 = blockIdx.x * per;
    int n1 = n0 + per;
    if (n1 > N_NODES) n1 = N_NODES;
    float acc = 0.f, z = 0.f;
    for (int n = n0; n < n1; n++) {
        float wgt = expf(g_logits[n] - gmax);
        acc += wgt * h[(size_t)n * 128 + t];
        z += wgt;
    }
    atomicAdd(&g_acc[t], acc);
    if (t == 0) atomicAdd(&g_acc[128], z);
}

__global__ void finalize_kernel(float* __restrict__ out) {
    int t = threadIdx.x;
    out[t] = g_acc[t] / g_acc[128];
}

// ---------------- launch -------------------------------------------------------------
extern "C" void kernel_launch(void* const* d_in, const int* in_sizes, int n_in,
                              void* d_out, int out_size) {
    const float* x       = (const float*)d_in[0];          // [100000, 300]
    const int*   nidx    = (const int*)d_in[1];            // hyper_edge_index[0]
    const int*   eidx    = ((const int*)d_in[1]) + NNZ;    // hyper_edge_index[1]
    const float* W1      = (const float*)d_in[2];          // [300,256]
    const float* b1      = (const float*)d_in[3];
    const float* W2      = (const float*)d_in[4];          // [256,256]
    const float* b2      = (const float*)d_in[5];
    const float* W3      = (const float*)d_in[6];          // [256,128]
    const float* b3      = (const float*)d_in[7];
    const float* attn_W  = (const float*)d_in[8];          // [128,1]
    const float* attn_b  = (const float*)d_in[9];          // [1]
    float* out = (float*)d_out;                            // [128]

    // 1-3: build + prep (slots so ncu -s5 -c1 captures launch #4 = agg_edge<300>)
    build_kernel<<<4096, 256>>>(nidx, eidx);
    prep_a_kernel<<<49, 256>>>();
    prep_b_kernel<<<1, 256>>>();

    // Layer 1: aggregate x (F=300) to edges, GEMM at edges, spread to nodes, lrelu
    agg_kernel<300, 3, 1, false><<<7500, 256>>>(x, g_eagg, nullptr);      // <- profiled
    sgemm_kernel<<<dim3(157, 4), 256>>>(g_eagg, W1, g_ew, N_EDGES, 300, 256);
    agg_kernel<256, 2, 0, true><<<25000, 256>>>(g_ew, g_h, b1);

    // Layer 2
    agg_kernel<256, 2, 1, false><<<5000, 256>>>(g_h, g_eagg, nullptr);
    sgemm_kernel<<<dim3(157, 4), 256>>>(g_eagg, W2, g_ew, N_EDGES, 256, 256);
    agg_kernel<256, 2, 0, true><<<25000, 256>>>(g_ew, g_h, b2);

    // Layer 3 (no activation)
    agg_kernel<256, 2, 1, false><<<5000, 256>>>(g_h, g_eagg, nullptr);
    sgemm_kernel<<<dim3(157, 2), 256>>>(g_eagg, W3, g_ew, N_EDGES, 256, 128);
    agg_kernel<128, 1, 0, false><<<12500, 256>>>(g_ew, g_h, b3);

    // Attention pooling (softmax over nodes, weighted sum -> [128])
    logits_kernel<<<12500, 256>>>(g_h, attn_W, attn_b);
    maxred_kernel<<<1, 1024>>>(12500);
    accum_kernel<<<512, 128>>>(g_h);
    finalize_kernel<<<1, 128>>>(out);
}

// round 6
// speedup vs baseline: 1.8368x; 1.6547x over previous
#include <cuda_runtime.h>
#include <cuda_fp16.h>

#define N_NODES 100000
#define N_EDGES 20000
#define NNZ     1600000
#define ESTRIDE 256   // max tracked nodes per edge (deg ~ Binomial mean 80, sd 9)
#define NSTRIDE 64    // max tracked edges per node (mean 16, sd 4)

// ---------------- scratch (device globals; zero-initialized at module load) ----------
__device__ float           g_eagg[(size_t)N_EDGES * 300];  // edge-agg feats (fp32, GEMM A)
__device__ __half          g_ew[(size_t)N_EDGES * 256];    // edge feats after W (fp16)
__device__ __half          g_h[(size_t)N_NODES * 256];     // node activations (fp16)
__device__ int             g_ecursor[N_EDGES];             // per-edge degree (zeroed by logits)
__device__ int             g_ncursor[N_NODES];             // per-node degree (zeroed by logits)
__device__ int             g_ebkt[(size_t)N_EDGES * ESTRIDE];   // node ids (32-bit)
__device__ unsigned short  g_nbkt[(size_t)N_NODES * NSTRIDE];   // edge ids (<20000 -> u16)
__device__ float           g_logits[N_NODES];
__device__ float           g_partmax[12500];
__device__ float           g_gmax;
__device__ float           g_acc[129];                     // [0..127] sum, [128]=Z

// unpack 4 fp16 (as uint2) -> float4 accumulate helper
static __device__ __forceinline__ void acc_h4(float4& acc, uint2 raw) {
    float2 f0 = __half22float2(*reinterpret_cast<__half2*>(&raw.x));
    float2 f1 = __half22float2(*reinterpret_cast<__half2*>(&raw.y));
    acc.x += f0.x; acc.y += f0.y; acc.z += f1.x; acc.w += f1.y;
}
static __device__ __forceinline__ uint2 pack_h4(float4 o) {
    __half2 v0 = __floats2half2_rn(o.x, o.y);
    __half2 v1 = __floats2half2_rn(o.z, o.w);
    uint2 pk;
    pk.x = *reinterpret_cast<unsigned*>(&v0);
    pk.y = *reinterpret_cast<unsigned*>(&v1);
    return pk;
}

// ---------------- bucket CSR build (cursors must be 0 on entry) ----------------------
__global__ void build_kernel(const int* __restrict__ nidx, const int* __restrict__ eidx) {
    int i = blockIdx.x * blockDim.x + threadIdx.x;
    int stride = gridDim.x * blockDim.x;
    for (int j = i; j < NNZ; j += stride) {
        int n = nidx[j];
        int e = eidx[j];
        int p = atomicAdd(&g_ecursor[e], 1);
        if (p < ESTRIDE) g_ebkt[(size_t)e * ESTRIDE + p] = n;
        int q = atomicAdd(&g_ncursor[n], 1);
        if (q < NSTRIDE) g_nbkt[(size_t)n * NSTRIDE + q] = (unsigned short)e;
    }
}

// ---------------- edge aggregation from fp32 source (layer 1: x) ---------------------
// warp per (edge, 128-feature chunk); 8 independent float4 gathers in flight
template <int F, int CHUNKS>
__global__ __launch_bounds__(256) void agg_edge_f32(const float* __restrict__ src,
                                                    float* __restrict__ dst) {
    int w = (blockIdx.x * blockDim.x + threadIdx.x) >> 5;
    int lane = threadIdx.x & 31;
    int row = w / CHUNKS;
    int ch  = w % CHUNKS;
    if (row >= N_EDGES) return;

    const int* __restrict__ lst = g_ebkt + (size_t)row * ESTRIDE;
    int tc  = g_ecursor[row];
    int cnt = tc < ESTRIDE ? tc : ESTRIDE;

    int colbase = ch * 128 + lane * 4;
    const bool active = colbase < F;            // partial last chunk for F=300
    const float* __restrict__ sp = src + colbase;

    float4 acc = make_float4(0.f, 0.f, 0.f, 0.f);
    int i = 0;
    for (; i + 8 <= cnt; i += 8) {
        int idxreg = 0;
        if (lane < 8) idxreg = lst[i + lane];
        int ns[8];
#pragma unroll
        for (int k = 0; k < 8; k++) ns[k] = __shfl_sync(0xffffffffu, idxreg, k);
        float4 t[8];
#pragma unroll
        for (int k = 0; k < 8; k++) {
            t[k] = make_float4(0.f, 0.f, 0.f, 0.f);
            if (active) t[k] = *(const float4*)(sp + (size_t)ns[k] * F);
        }
#pragma unroll
        for (int k = 0; k < 8; k++) {
            acc.x += t[k].x; acc.y += t[k].y; acc.z += t[k].z; acc.w += t[k].w;
        }
    }
    for (; i < cnt; i++) {
        int n = lst[i];
        if (active) {
            float4 t = *(const float4*)(sp + (size_t)n * F);
            acc.x += t.x; acc.y += t.y; acc.z += t.z; acc.w += t.w;
        }
    }
    if (!active) return;
    float inv = (tc > 0) ? 1.0f / (float)tc : 0.0f;
    float4 o = make_float4(acc.x * inv, acc.y * inv, acc.z * inv, acc.w * inv);
    *(float4*)(dst + (size_t)row * F + colbase) = o;
}

// ---------------- edge aggregation from fp16 source (layers 2-3: h) ------------------
template <int F, int CHUNKS>
__global__ __launch_bounds__(256) void agg_edge_f16(const __half* __restrict__ src,
                                                    float* __restrict__ dst) {
    int w = (blockIdx.x * blockDim.x + threadIdx.x) >> 5;
    int lane = threadIdx.x & 31;
    int row = w / CHUNKS;
    int ch  = w % CHUNKS;
    if (row >= N_EDGES) return;

    const int* __restrict__ lst = g_ebkt + (size_t)row * ESTRIDE;
    int tc  = g_ecursor[row];
    int cnt = tc < ESTRIDE ? tc : ESTRIDE;

    int colbase = ch * 128 + lane * 4;                 // F multiple of 128 -> always active
    const __half* __restrict__ sp = src + colbase;

    float4 acc = make_float4(0.f, 0.f, 0.f, 0.f);
    int i = 0;
    for (; i + 8 <= cnt; i += 8) {
        int idxreg = 0;
        if (lane < 8) idxreg = lst[i + lane];
        int ns[8];
#pragma unroll
        for (int k = 0; k < 8; k++) ns[k] = __shfl_sync(0xffffffffu, idxreg, k);
        uint2 raw[8];
#pragma unroll
        for (int k = 0; k < 8; k++) raw[k] = *(const uint2*)(sp + (size_t)ns[k] * F);
#pragma unroll
        for (int k = 0; k < 8; k++) acc_h4(acc, raw[k]);
    }
    for (; i < cnt; i++) {
        uint2 raw = *(const uint2*)(sp + (size_t)lst[i] * F);
        acc_h4(acc, raw);
    }
    float inv = (tc > 0) ? 1.0f / (float)tc : 0.0f;
    float4 o = make_float4(acc.x * inv, acc.y * inv, acc.z * inv, acc.w * inv);
    *(float4*)(dst + (size_t)row * F + colbase) = o;
}

// ---------------- node aggregation: fp16 ew -> fp16 h, +bias, optional lrelu ---------
template <int F, int CHUNKS, bool LRELU>
__global__ __launch_bounds__(256) void agg_node_f16(const __half* __restrict__ src,
                                                    __half* __restrict__ dst,
                                                    const float* __restrict__ bias) {
    int w = (blockIdx.x * blockDim.x + threadIdx.x) >> 5;
    int lane = threadIdx.x & 31;
    int row = w / CHUNKS;
    int ch  = w % CHUNKS;
    if (row >= N_NODES) return;

    const unsigned short* __restrict__ lst = g_nbkt + (size_t)row * NSTRIDE;
    int tc  = g_ncursor[row];
    int cnt = tc < NSTRIDE ? tc : NSTRIDE;

    int colbase = ch * 128 + lane * 4;
    const __half* __restrict__ sp = src + colbase;

    float4 acc = make_float4(0.f, 0.f, 0.f, 0.f);
    int i = 0;
    for (; i + 8 <= cnt; i += 8) {
        int idxreg = 0;
        if (lane < 8) idxreg = (int)lst[i + lane];
        int ns[8];
#pragma unroll
        for (int k = 0; k < 8; k++) ns[k] = __shfl_sync(0xffffffffu, idxreg, k);
        uint2 raw[8];
#pragma unroll
        for (int k = 0; k < 8; k++) raw[k] = *(const uint2*)(sp + (size_t)ns[k] * F);
#pragma unroll
        for (int k = 0; k < 8; k++) acc_h4(acc, raw[k]);
    }
    for (; i < cnt; i++) {
        uint2 raw = *(const uint2*)(sp + (size_t)lst[i] * F);
        acc_h4(acc, raw);
    }
    float inv = (tc > 0) ? 1.0f / (float)tc : 0.0f;
    float4 bb = *(const float4*)(bias + colbase);
    float4 o;
    o.x = acc.x * inv + bb.x;
    o.y = acc.y * inv + bb.y;
    o.z = acc.z * inv + bb.z;
    o.w = acc.w * inv + bb.w;
    if (LRELU) {
        o.x = (o.x > 0.f) ? o.x : 0.01f * o.x;
        o.y = (o.y > 0.f) ? o.y : 0.01f * o.y;
        o.z = (o.z > 0.f) ? o.z : 0.01f * o.z;
        o.w = (o.w > 0.f) ? o.w : 0.01f * o.w;
    }
    *(uint2*)(dst + (size_t)row * F + colbase) = pack_h4(o);
}

// ---------------- fp32 SGEMM, fp16 output: C[M,N] = A[M,K] @ B[K,N] ------------------
__global__ __launch_bounds__(256) void sgemm_kernel(const float* __restrict__ A,
                                                    const float* __restrict__ B,
                                                    __half* __restrict__ C,
                                                    int M, int K, int N) {
    __shared__ float As[8][136];
    __shared__ float Bs[8][64];
    const int tid = threadIdx.x;
    const int bm = blockIdx.x * 128;
    const int bn = blockIdx.y * 64;
    const int a_row = tid >> 1;
    const int a_col = (tid & 1) * 4;
    const int b_row = tid >> 5;
    const int b_col = (tid & 31) * 2;
    const int ty = tid >> 4;
    const int tx = tid & 15;
    float acc[8][4];
#pragma unroll
    for (int i = 0; i < 8; i++)
#pragma unroll
        for (int j = 0; j < 4; j++) acc[i][j] = 0.f;

    const bool arow_ok = (bm + a_row) < M;
    const float* Ab = A + (size_t)(bm + a_row) * K;

    for (int kt = 0; kt < K; kt += 8) {
#pragma unroll
        for (int j = 0; j < 4; j++) {
            int k = kt + a_col + j;
            As[a_col + j][a_row] = (arow_ok && k < K) ? Ab[k] : 0.f;
        }
        {
            int k = kt + b_row;
            float2 bv = make_float2(0.f, 0.f);
            if (k < K) bv = *(const float2*)(B + (size_t)k * N + bn + b_col);
            *(float2*)&Bs[b_row][b_col] = bv;
        }
        __syncthreads();
#pragma unroll
        for (int k = 0; k < 8; k++) {
            float4 a0 = *(const float4*)&As[k][ty * 8];
            float4 a1 = *(const float4*)&As[k][ty * 8 + 4];
            float4 bv = *(const float4*)&Bs[k][tx * 4];
            float a[8] = {a0.x, a0.y, a0.z, a0.w, a1.x, a1.y, a1.z, a1.w};
            float b[4] = {bv.x, bv.y, bv.z, bv.w};
#pragma unroll
            for (int i = 0; i < 8; i++)
#pragma unroll
                for (int j = 0; j < 4; j++) acc[i][j] += a[i] * b[j];
        }
        __syncthreads();
    }
#pragma unroll
    for (int i = 0; i < 8; i++) {
        int r = bm + ty * 8 + i;
        if (r < M) {
            float4 o = make_float4(acc[i][0], acc[i][1], acc[i][2], acc[i][3]);
            *(uint2*)(C + (size_t)r * N + bn + tx * 4) = pack_h4(o);
        }
    }
}

// ---------------- attention epilogue (h is fp16, stride 128) -------------------------
// Also zeroes bucket cursors for the next replay.
__global__ void logits_kernel(const __half* __restrict__ h,
                              const float* __restrict__ aw, const float* __restrict__ ab) {
    __shared__ float smax[8];
    int gidx = blockIdx.x * blockDim.x + threadIdx.x;
    int gstride = gridDim.x * blockDim.x;
    for (int j = gidx; j < N_EDGES; j += gstride) g_ecursor[j] = 0;
    for (int j = gidx; j < N_NODES; j += gstride) g_ncursor[j] = 0;

    int w = gidx >> 5;
    int lane = threadIdx.x & 31;
    float lg = -1e30f;
    if (w < N_NODES) {
        uint2 raw = *(const uint2*)(h + (size_t)w * 128 + lane * 4);
        float2 f0 = __half22float2(*reinterpret_cast<__half2*>(&raw.x));
        float2 f1 = __half22float2(*reinterpret_cast<__half2*>(&raw.y));
        float4 wv = ((const float4*)aw)[lane];
        float d = f0.x * wv.x + f0.y * wv.y + f1.x * wv.z + f1.y * wv.w;
#pragma unroll
        for (int off = 16; off > 0; off >>= 1) d += __shfl_xor_sync(0xffffffffu, d, off);
        d += ab[0];
        if (lane == 0) g_logits[w] = d;
        lg = d;
    }
    int wl = threadIdx.x >> 5;
    if (lane == 0) smax[wl] = lg;
    __syncthreads();
    if (threadIdx.x == 0) {
        float m = smax[0];
#pragma unroll
        for (int j = 1; j < 8; j++) m = fmaxf(m, smax[j]);
        g_partmax[blockIdx.x] = m;
    }
}

// global max of logits; also zeroes g_acc for the upcoming accum
__global__ void maxred_kernel(int nparts) {
    __shared__ float sm[32];
    if (threadIdx.x < 129) g_acc[threadIdx.x] = 0.0f;
    float m = -1e30f;
    for (int i = threadIdx.x; i < nparts; i += 1024) m = fmaxf(m, g_partmax[i]);
#pragma unroll
    for (int off = 16; off > 0; off >>= 1) m = fmaxf(m, __shfl_xor_sync(0xffffffffu, m, off));
    if ((threadIdx.x & 31) == 0) sm[threadIdx.x >> 5] = m;
    __syncthreads();
    if (threadIdx.x < 32) {
        float v = sm[threadIdx.x];
#pragma unroll
        for (int off = 16; off > 0; off >>= 1) v = fmaxf(v, __shfl_xor_sync(0xffffffffu, v, off));
        if (threadIdx.x == 0) g_gmax = v;
    }
}

__global__ void accum_kernel(const __half* __restrict__ h) {
    int t = threadIdx.x;           // 0..127 feature column
    float gmax = g_gmax;
    int per = (N_NODES + gridDim.x - 1) / gridDim.x;
    int n0 = blockIdx.x * per;
    int n1 = n0 + per;
    if (n1 > N_NODES) n1 = N_NODES;
    float acc = 0.f, z = 0.f;
    for (int n = n0; n < n1; n++) {
        float wgt = expf(g_logits[n] - gmax);
        acc += wgt * __half2float(h[(size_t)n * 128 + t]);
        z += wgt;
    }
    atomicAdd(&g_acc[t], acc);
    if (t == 0) atomicAdd(&g_acc[128], z);
}

__global__ void finalize_kernel(float* __restrict__ out) {
    int t = threadIdx.x;
    out[t] = g_acc[t] / g_acc[128];
}

// ---------------- launch -------------------------------------------------------------
extern "C" void kernel_launch(void* const* d_in, const int* in_sizes, int n_in,
                              void* d_out, int out_size) {
    const float* x       = (const float*)d_in[0];          // [100000, 300]
    const int*   nidx    = (const int*)d_in[1];            // hyper_edge_index[0]
    const int*   eidx    = ((const int*)d_in[1]) + NNZ;    // hyper_edge_index[1]
    const float* W1      = (const float*)d_in[2];          // [300,256]
    const float* b1      = (const float*)d_in[3];
    const float* W2      = (const float*)d_in[4];          // [256,256]
    const float* b2      = (const float*)d_in[5];
    const float* W3      = (const float*)d_in[6];          // [256,128]
    const float* b3      = (const float*)d_in[7];
    const float* attn_W  = (const float*)d_in[8];          // [128,1]
    const float* attn_b  = (const float*)d_in[9];          // [1]
    float* out = (float*)d_out;                            // [128]

    // Layer 1 (launch slots 1-4; ncu -s5 -c1 captures slot 4 = agg_node_f16<256>)
    build_kernel<<<4096, 256>>>(nidx, eidx);
    agg_edge_f32<300, 3><<<7500, 256>>>(x, g_eagg);
    sgemm_kernel<<<dim3(157, 4), 256>>>(g_eagg, W1, g_ew, N_EDGES, 300, 256);
    agg_node_f16<256, 2, true><<<25000, 256>>>(g_ew, g_h, b1);    // <- capture

    // Layer 2
    agg_edge_f16<256, 2><<<5000, 256>>>(g_h, g_eagg);
    sgemm_kernel<<<dim3(157, 4), 256>>>(g_eagg, W2, g_ew, N_EDGES, 256, 256);
    agg_node_f16<256, 2, true><<<25000, 256>>>(g_ew, g_h, b2);

    // Layer 3 (no activation)
    agg_edge_f16<256, 2><<<5000, 256>>>(g_h, g_eagg);
    sgemm_kernel<<<dim3(157, 2), 256>>>(g_eagg, W3, g_ew, N_EDGES, 256, 128);
    agg_node_f16<128, 1, false><<<12500, 256>>>(g_ew, g_h, b3);

    // Attention pooling (softmax over nodes, weighted sum -> [128])
    logits_kernel<<<12500, 256>>>(g_h, attn_W, attn_b);
    maxred_kernel<<<1, 1024>>>(12500);
    accum_kernel<<<512, 128>>>(g_h);
    finalize_kernel<<<1, 128>>>(out);
}